// round 12
// baseline (speedup 1.0000x reference)
#include <cuda_runtime.h>
#include <cuda_fp16.h>
#include <cstdint>
#include <math.h>

// ---------------- problem constants ----------------
#define NTOK 4096
#define DDIM 2048
#define HDIM 1408
#define NE   16
#define NS   2
#define NSLOT (NE + NS)
#define TOPK 2
#define TM 128
#define TN 128
#define KC 32
#define MAXROWS (NTOK*TOPK + NE*TM + NTOK*NS)   // 18432
#define MAXTILESM (MAXROWS / TM)                // 144
#define NBN1 (HDIM / TN)     // 11
#define NCH1 (DDIM / KC)     // 64
#define NBN2 (DDIM / TN)     // 16
#define NCH2 (HDIM / KC)     // 44
#define WCH  4096            // weight chunk elems: 128n x 32k fp16
#define ACH  4096            // hidden chunk elems: 128m x 32k fp16

// smem tile geometry: rows of 32 fp16 + 16 pad = 80 bytes
#define PITCH 80
#define TILEB (128 * PITCH)          // 10240 B
#define OFF_TOK 0
#define OFF_W   512
#define OFF_TILES 1024
#define AOF(b) (OFF_TILES + (b)*2*TILEB)
#define BOF(b) (AOF(b) + TILEB)
#define SMEM_BYTES (OFF_TILES + 4*TILEB)   // 41984

// ---------------- device scratch (tiled layouts) ----------------
__device__ __align__(16) __half g_w1t[(size_t)NSLOT * NBN1 * NCH1 * WCH];
__device__ __align__(16) __half g_w2t[(size_t)NSLOT * NBN2 * NCH2 * WCH];
__device__ __align__(16) __half g_xc[(size_t)NTOK * NCH1 * 32];     // [tok][c][32]
__device__ __align__(16) __half g_hid[(size_t)MAXTILESM * NCH2 * ACH];
__device__ int   g_row_token[MAXROWS];
__device__ float g_row_w[MAXROWS];
__device__ int   g_tile_slot[MAXTILESM];
__device__ int   g_topk_i[NTOK * TOPK];
__device__ float g_topk_w[NTOK * TOPK];
__device__ int   g_counts[NE];
__device__ int   g_fill[NE];
__device__ int   g_offsets[NSLOT];
__device__ float g_psum[NE];
__device__ float g_lsum[NE];

// ---------------- helpers ----------------
__device__ __forceinline__ uint32_t smem_u32(const void* p) {
    uint32_t a;
    asm("{ .reg .u64 t; cvta.to.shared.u64 t, %1; cvt.u32.u64 %0, t; }"
        : "=r"(a) : "l"(p));
    return a;
}
__device__ __forceinline__ void ldsm4(uint32_t* r, uint32_t addr) {
    asm volatile("ldmatrix.sync.aligned.m8n8.x4.shared.b16 {%0,%1,%2,%3}, [%4];"
                 : "=r"(r[0]), "=r"(r[1]), "=r"(r[2]), "=r"(r[3]) : "r"(addr));
}
// fp16-accumulator mma: accumulate form
__device__ __forceinline__ void mma_h_acc(uint32_t* d, const uint32_t* a, const uint32_t* b) {
    asm volatile("mma.sync.aligned.m16n8k16.row.col.f16.f16.f16.f16 "
                 "{%0,%1}, {%2,%3,%4,%5}, {%6,%7}, {%0,%1};"
                 : "+r"(d[0]), "+r"(d[1])
                 : "r"(a[0]), "r"(a[1]), "r"(a[2]), "r"(a[3]), "r"(b[0]), "r"(b[1]));
}
// fp16-accumulator mma: C = 0 form (starts a fresh chunk, no explicit zeroing)
__device__ __forceinline__ void mma_h_zero(uint32_t* d, const uint32_t* a, const uint32_t* b) {
    asm volatile("mma.sync.aligned.m16n8k16.row.col.f16.f16.f16.f16 "
                 "{%0,%1}, {%2,%3,%4,%5}, {%6,%7}, {%8,%9};"
                 : "=r"(d[0]), "=r"(d[1])
                 : "r"(a[0]), "r"(a[1]), "r"(a[2]), "r"(a[3]), "r"(b[0]), "r"(b[1]),
                   "r"(0u), "r"(0u));
}
__device__ __forceinline__ uint32_t pkh(__half a, __half b) {
    return (uint32_t)__half_as_ushort(a) | ((uint32_t)__half_as_ushort(b) << 16);
}

// ------- weight transpose + fp16 round into tiled layout --------------------
template <int PH>
__global__ void conv_w(const float* __restrict__ ew, const float* __restrict__ sw) {
    const int K = (PH == 1) ? DDIM : HDIM;
    const int N = (PH == 1) ? HDIM : DDIM;
    const int NBN = (PH == 1) ? NBN1 : NBN2;
    const int NCH = (PH == 1) ? NCH1 : NCH2;
    __half* dst = (PH == 1) ? g_w1t : g_w2t;
    int slot = blockIdx.z;
    const float* src = (slot < NE) ? ew + (size_t)slot * K * N
                                   : sw + (size_t)(slot - NE) * K * N;
    __shared__ float t[32][33];
    int k0 = blockIdx.x * 32, n0 = blockIdx.y * 32;
    int tx = threadIdx.x, ty = threadIdx.y;   // 32, 8
#pragma unroll
    for (int i = 0; i < 4; i++)
        t[ty + i * 8][tx] = src[(size_t)(k0 + ty + i * 8) * N + n0 + tx];
    __syncthreads();
    const int c = k0 >> 5;
#pragma unroll
    for (int i = 0; i < 4; i++) {
        int n = n0 + ty + i * 8;
        float v = t[tx][ty + i * 8];                 // src[k0+tx][n]
        size_t base = ((size_t)(slot * NBN + (n >> 7)) * NCH + c) * WCH
                      + (size_t)(n & 127) * 32 + tx;
        dst[base] = __float2half_rn(v);
    }
}

// ---------------- x fp16 round (layout = linear per token) ------------------
__global__ void conv_x(const float* __restrict__ x) {
    size_t i = ((size_t)blockIdx.x * blockDim.x + threadIdx.x) * 4;
    if (i >= (size_t)NTOK * DDIM) return;
    float4 v = *(const float4*)(x + i);
    *(uint2*)(g_xc + i) = make_uint2(
        pkh(__float2half_rn(v.x), __float2half_rn(v.y)),
        pkh(__float2half_rn(v.z), __float2half_rn(v.w)));
}

// ---------------- init ----------------
__global__ void init_kernel(float* __restrict__ out) {
    int idx = blockIdx.x * blockDim.x + threadIdx.x;
    int stride = gridDim.x * blockDim.x;
    for (size_t i = idx; i < (size_t)NTOK * DDIM; i += stride) out[i] = 0.0f;
    for (int i = idx; i < MAXROWS; i += stride) g_row_token[i] = -1;
    if (idx < NE) {
        g_counts[idx] = 0; g_fill[idx] = 0;
        g_psum[idx] = 0.0f; g_lsum[idx] = 0.0f;
    }
}

// ---------------- router ----------------
__global__ void router_kernel(const float* __restrict__ x,
                              const float* __restrict__ gw) {
    int t = blockIdx.x;
    int tid = threadIdx.x;
    float acc[NE];
#pragma unroll
    for (int e = 0; e < NE; e++) acc[e] = 0.0f;
    const float* xr = x + (size_t)t * DDIM;
    for (int d = tid; d < DDIM; d += 128) {
        float xv = xr[d];
        const float* g = gw + d * NE;
#pragma unroll
        for (int e = 0; e < NE; e++) acc[e] += xv * g[e];
    }
    __shared__ float red[128][NE + 1];
#pragma unroll
    for (int e = 0; e < NE; e++) red[tid][e] = acc[e];
    __syncthreads();
    for (int off = 64; off > 0; off >>= 1) {
        if (tid < off) {
#pragma unroll
            for (int e = 0; e < NE; e++) red[tid][e] += red[tid + off][e];
        }
        __syncthreads();
    }
    if (tid == 0) {
        float lg[NE], p[NE];
        float m = -1e30f;
#pragma unroll
        for (int e = 0; e < NE; e++) { lg[e] = red[0][e]; m = fmaxf(m, lg[e]); }
        float s = 0.0f;
#pragma unroll
        for (int e = 0; e < NE; e++) { p[e] = expf(lg[e] - m); s += p[e]; }
        float inv = 1.0f / s;
#pragma unroll
        for (int e = 0; e < NE; e++) p[e] *= inv;
        int i1 = 0;
#pragma unroll
        for (int e = 1; e < NE; e++) if (p[e] > p[i1]) i1 = e;
        int i2 = (i1 == 0) ? 1 : 0;
#pragma unroll
        for (int e = 0; e < NE; e++) if (e != i1 && p[e] > p[i2]) i2 = e;
        float wsum = p[i1] + p[i2];
        g_topk_i[t * 2 + 0] = i1;
        g_topk_i[t * 2 + 1] = i2;
        g_topk_w[t * 2 + 0] = p[i1] / wsum;
        g_topk_w[t * 2 + 1] = p[i2] / wsum;
        atomicAdd(&g_counts[i1], 1);
        atomicAdd(&g_counts[i2], 1);
#pragma unroll
        for (int e = 0; e < NE; e++) {
            atomicAdd(&g_psum[e], p[e]);
            atomicAdd(&g_lsum[e], lg[e]);
        }
    }
}

// ---------------- schedule ----------------
__global__ void schedule_kernel(float* __restrict__ out, long long out_size) {
    if (threadIdx.x != 0 || blockIdx.x != 0) return;
    int tile = 0;
    for (int slot = 0; slot < NSLOT; slot++) {
        int cnt = (slot < NE) ? g_counts[slot] : NTOK;
        g_offsets[slot] = tile * TM;
        int nt = (cnt + TM - 1) / TM;
        for (int i = 0; i < nt; i++) g_tile_slot[tile++] = slot;
    }
    for (; tile < MAXTILESM; tile++) g_tile_slot[tile] = -1;
    float aux = 0.0f;
    for (int e = 0; e < NE; e++)
        aux += (g_psum[e] * (1.0f / NTOK)) * (g_lsum[e] * (1.0f / NTOK));
    aux *= (float)NE;
    if (out_size > (long long)NTOK * DDIM) out[(size_t)NTOK * DDIM] = aux;
}

// ---------------- scatter ----------------
__global__ void scatter_kernel() {
    int i = blockIdx.x * blockDim.x + threadIdx.x;
    const int total = NTOK * TOPK + NTOK * NS;
    if (i >= total) return;
    if (i < NTOK * TOPK) {
        int e = g_topk_i[i];
        int pos = atomicAdd(&g_fill[e], 1);
        int row = g_offsets[e] + pos;
        g_row_token[row] = i >> 1;
        g_row_w[row] = g_topk_w[i];
    } else {
        int j = i - NTOK * TOPK;
        int s = j / NTOK, t = j % NTOK;
        int row = g_offsets[NE + s] + t;
        g_row_token[row] = t;
        g_row_w[row] = 1.0f;
    }
}

// ----- fp16 grouped FFN GEMM; fp16 accumulators + per-chunk fp32 promote ----
// 512 threads, 16 warps (4m x 4n), 32x32 warp tiles.
// PHASE1: hidden = silu(gather(x) @ W1)   K=DDIM -> g_hid (tiled fp16)
// PHASE2: out   += w_row * (hidden @ W2)  K=HDIM (atomicAdd)
template <bool PHASE1>
__global__ __launch_bounds__(512, 1)
void ffn_mma(float* __restrict__ out) {
    extern __shared__ char smem[];
    const int bm = blockIdx.x, bn = blockIdx.y;
    const int slot = g_tile_slot[bm];
    if (slot < 0) return;
    const int NC = PHASE1 ? NCH1 : NCH2;
    const int row0 = bm * TM, n0 = bn * TN;
    const int tid = threadIdx.x, wid = tid >> 5, lane = tid & 31;
    int* s_tok = (int*)(smem + OFF_TOK);
    float* s_w = (float*)(smem + OFF_W);
    if (tid < TM) {
        s_tok[tid] = g_row_token[row0 + tid];
        s_w[tid]   = g_row_w[row0 + tid];
    }
    __syncthreads();

    // ---- loader: tile = 512 u4/chunk, 1 per thread ----
    const int tDst = (tid >> 2) * PITCH + (tid & 3) * 16;

    const uint4* srcB = PHASE1
        ? (const uint4*)g_w1t + (size_t)(slot * NBN1 + bn) * NCH1 * 512 + tid
        : (const uint4*)g_w2t + (size_t)(slot * NBN2 + bn) * NCH2 * 512 + tid;
    const uint4* srcA;
    int aStride;
    if (PHASE1) {
        int tok = s_tok[tid >> 2]; if (tok < 0) tok = 0;
        srcA = (const uint4*)(g_xc + (size_t)tok * NCH1 * 32) + (tid & 3);
        aStride = 4;
    } else {
        srcA = (const uint4*)g_hid + (size_t)bm * NCH2 * 512 + tid;
        aStride = 512;
    }

    const uint32_t sb = smem_u32(smem);
    const int warp_m = (wid >> 2) * 32;
    const int warp_n = (wid & 3) * 32;
    const int a_row = warp_m + (lane & 15);
    const int a_c8  = (lane >> 4) << 3;
    const int b_row = warp_n + (lane & 7) + ((lane >> 4) << 3);
    const int b_c8  = lane & 8;

    float acc[2][4][4];          // fp32 master accumulators
#pragma unroll
    for (int i = 0; i < 2; i++)
#pragma unroll
        for (int j = 0; j < 4; j++)
#pragma unroll
            for (int k = 0; k < 4; k++) acc[i][j][k] = 0.0f;

    // -------- direct load of chunk 0 --------
    *(uint4*)(smem + AOF(0) + tDst) = srcA[0];
    *(uint4*)(smem + BOF(0) + tDst) = srcB[0];
    __syncthreads();

    // -------- main loop --------
    for (int c = 0; c < NC; c++) {
        const int buf = c & 1;
        const bool have = (c + 1 < NC);

        uint4 sA, sB;
        if (have) {
            sA = srcA[(size_t)(c + 1) * aStride];
            sB = srcB[(size_t)(c + 1) * 512];
        }

        // ---- compute on buffer `buf`: fp16 accumulate over the chunk ----
        uint32_t acch[2][4][2];
        {
            const uint32_t ab = sb + AOF(buf);
            const uint32_t bb = sb + BOF(buf);
#pragma unroll
            for (int ks = 0; ks < 2; ks++) {
                const int kk = ks * 16;
                const uint32_t baddr = (uint32_t)(b_row * PITCH + (kk + b_c8) * 2);
                const uint32_t aaddr = (uint32_t)(a_row * PITCH + (kk + a_c8) * 2);
                uint32_t bh0[4], bh1[4];
                ldsm4(bh0, bb + baddr);
                ldsm4(bh1, bb + baddr + 16 * PITCH);
#pragma unroll
                for (int mi = 0; mi < 2; mi++) {
                    uint32_t af[4];
                    ldsm4(af, ab + aaddr + mi * 16 * PITCH);
                    if (ks == 0) {
                        mma_h_zero(acch[mi][0], af, bh0);
                        mma_h_zero(acch[mi][1], af, bh0 + 2);
                        mma_h_zero(acch[mi][2], af, bh1);
                        mma_h_zero(acch[mi][3], af, bh1 + 2);
                    } else {
                        mma_h_acc(acch[mi][0], af, bh0);
                        mma_h_acc(acch[mi][1], af, bh0 + 2);
                        mma_h_acc(acch[mi][2], af, bh1);
                        mma_h_acc(acch[mi][3], af, bh1 + 2);
                    }
                }
            }
        }

        // ---- promote chunk result into fp32 masters (overlaps mma pipe) ----
#pragma unroll
        for (int mi = 0; mi < 2; mi++)
#pragma unroll
            for (int nf = 0; nf < 4; nf++) {
                float2 f0 = __half22float2(*(__half2*)&acch[mi][nf][0]);
                float2 f1 = __half22float2(*(__half2*)&acch[mi][nf][1]);
                acc[mi][nf][0] += f0.x; acc[mi][nf][1] += f0.y;
                acc[mi][nf][2] += f1.x; acc[mi][nf][3] += f1.y;
            }

        // ---- STS staged chunk into other buffer ----
        if (have) {
            const int nb = (c + 1) & 1;
            *(uint4*)(smem + AOF(nb) + tDst) = sA;
            *(uint4*)(smem + BOF(nb) + tDst) = sB;
        }
        __syncthreads();
    }

    // -------- epilogue --------
    const int gid = lane >> 2, tig = lane & 3;
#pragma unroll
    for (int mi = 0; mi < 2; mi++) {
#pragma unroll
        for (int f = 0; f < 4; f++) {
            const int col = n0 + warp_n + f * 8 + tig * 2;
#pragma unroll
            for (int h = 0; h < 2; h++) {
                const int r = warp_m + mi * 16 + gid + h * 8;
                float v0 = acc[mi][f][2 * h];
                float v1 = acc[mi][f][2 * h + 1];
                if (PHASE1) {
                    v0 = v0 / (1.0f + __expf(-v0));
                    v1 = v1 / (1.0f + __expf(-v1));
                    size_t base = ((size_t)bm * NCH2 + (col >> 5)) * ACH
                                  + (size_t)r * 32 + (col & 31);
                    *(uint32_t*)(g_hid + base) =
                        pkh(__float2half_rn(v0), __float2half_rn(v1));
                } else {
                    int tok = s_tok[r];
                    if (tok >= 0) {
                        float w = s_w[r];
                        float* op = out + (size_t)tok * DDIM + col;
                        atomicAdd(op,     w * v0);
                        atomicAdd(op + 1, w * v1);
                    }
                }
            }
        }
    }
}

// ---------------- launch ----------------
extern "C" void kernel_launch(void* const* d_in, const int* in_sizes, int n_in,
                              void* d_out, int out_size) {
    const float* x   = (const float*)d_in[0];
    const float* gw  = (const float*)d_in[1];
    const float* sw1 = (const float*)d_in[2];
    const float* sw2 = (const float*)d_in[3];
    const float* ew1 = (const float*)d_in[4];
    const float* ew2 = (const float*)d_in[5];
    float* out = (float*)d_out;

    cudaFuncSetAttribute(ffn_mma<true>,  cudaFuncAttributeMaxDynamicSharedMemorySize, SMEM_BYTES);
    cudaFuncSetAttribute(ffn_mma<false>, cudaFuncAttributeMaxDynamicSharedMemorySize, SMEM_BYTES);

    init_kernel<<<1024, 256>>>(out);
    router_kernel<<<NTOK, 128>>>(x, gw);
    schedule_kernel<<<1, 32>>>(out, (long long)out_size);
    scatter_kernel<<<(NTOK * (TOPK + NS) + 255) / 256, 256>>>();

    dim3 tb(32, 8);
    conv_w<1><<<dim3(DDIM / 32, HDIM / 32, NSLOT), tb>>>(ew1, sw1);
    conv_w<2><<<dim3(HDIM / 32, DDIM / 32, NSLOT), tb>>>(ew2, sw2);
    conv_x<<<(NTOK * DDIM / 4 + 255) / 256, 256>>>(x);

    dim3 g1(MAXTILESM, NBN1);   // 144 x 11
    dim3 g2(MAXTILESM, NBN2);   // 144 x 16
    ffn_mma<true ><<<g1, 512, SMEM_BYTES>>>(out);
    ffn_mma<false><<<g2, 512, SMEM_BYTES>>>(out);
}

// round 13
// speedup vs baseline: 1.2252x; 1.2252x over previous
#include <cuda_runtime.h>
#include <cuda_fp16.h>
#include <cstdint>
#include <math.h>

// ---------------- problem constants ----------------
#define NTOK 4096
#define DDIM 2048
#define HDIM 1408
#define NE   16
#define NS   2
#define NSLOT (NE + NS)
#define TOPK 2
#define TM 128
#define TN 128
#define KC 32
#define MAXROWS (NTOK*TOPK + NE*TM + NTOK*NS)   // 18432
#define MAXTILESM (MAXROWS / TM)                // 144
#define NBN1 (HDIM / TN)     // 11
#define NCH1 (DDIM / KC)     // 64
#define NBN2 (DDIM / TN)     // 16
#define NCH2 (HDIM / KC)     // 44
#define ACH  4096            // hidden chunk elems: 128m x 32k fp16

// smem tile geometry: rows of 32 fp16 + 16 pad = 80 bytes
#define PITCH 80
#define TILEB (128 * PITCH)          // 10240 B
#define OFF_TOK 0
#define OFF_W   512
#define OFF_TILES 1024
#define AOF(b) (OFF_TILES + (b)*2*TILEB)
#define BOF(b) (AOF(b) + TILEB)
#define SMEM_BYTES (OFF_TILES + 4*TILEB)   // 41984

// ---------------- device scratch ----------------
__device__ __align__(16) __half g_hid[(size_t)MAXTILESM * NCH2 * ACH];
__device__ int   g_row_token[MAXROWS];
__device__ float g_row_w[MAXROWS];
__device__ int   g_tile_slot[MAXTILESM];
__device__ int   g_topk_i[NTOK * TOPK];
__device__ float g_topk_w[NTOK * TOPK];
__device__ int   g_counts[NE];
__device__ int   g_fill[NE];
__device__ int   g_offsets[NSLOT];
__device__ float g_psum[NE];
__device__ float g_lsum[NE];

// ---------------- helpers ----------------
__device__ __forceinline__ uint32_t smem_u32(const void* p) {
    uint32_t a;
    asm("{ .reg .u64 t; cvta.to.shared.u64 t, %1; cvt.u32.u64 %0, t; }"
        : "=r"(a) : "l"(p));
    return a;
}
__device__ __forceinline__ void ldsm4(uint32_t* r, uint32_t addr) {
    asm volatile("ldmatrix.sync.aligned.m8n8.x4.shared.b16 {%0,%1,%2,%3}, [%4];"
                 : "=r"(r[0]), "=r"(r[1]), "=r"(r[2]), "=r"(r[3]) : "r"(addr));
}
__device__ __forceinline__ void mmaf16(float* d, const uint32_t* a, const uint32_t* b) {
    asm volatile("mma.sync.aligned.m16n8k16.row.col.f32.f16.f16.f32 "
                 "{%0,%1,%2,%3}, {%4,%5,%6,%7}, {%8,%9}, {%0,%1,%2,%3};"
                 : "+f"(d[0]), "+f"(d[1]), "+f"(d[2]), "+f"(d[3])
                 : "r"(a[0]), "r"(a[1]), "r"(a[2]), "r"(a[3]), "r"(b[0]), "r"(b[1]));
}
__device__ __forceinline__ uint32_t pkh(__half a, __half b) {
    return (uint32_t)__half_as_ushort(a) | ((uint32_t)__half_as_ushort(b) << 16);
}
__device__ __forceinline__ uint32_t pk2f(float a, float b) {
    __half2 h = __floats2half2_rn(a, b);
    return *(uint32_t*)&h;
}

// ---------------- init ----------------
__global__ void init_kernel(float* __restrict__ out) {
    int idx = blockIdx.x * blockDim.x + threadIdx.x;
    int stride = gridDim.x * blockDim.x;
    for (size_t i = idx; i < (size_t)NTOK * DDIM; i += stride) out[i] = 0.0f;
    for (int i = idx; i < MAXROWS; i += stride) g_row_token[i] = -1;
    if (idx < NE) {
        g_counts[idx] = 0; g_fill[idx] = 0;
        g_psum[idx] = 0.0f; g_lsum[idx] = 0.0f;
    }
}

// ---------------- router ----------------
__global__ void router_kernel(const float* __restrict__ x,
                              const float* __restrict__ gw) {
    int t = blockIdx.x;
    int tid = threadIdx.x;
    float acc[NE];
#pragma unroll
    for (int e = 0; e < NE; e++) acc[e] = 0.0f;
    const float* xr = x + (size_t)t * DDIM;
    for (int d = tid; d < DDIM; d += 128) {
        float xv = xr[d];
        const float* g = gw + d * NE;
#pragma unroll
        for (int e = 0; e < NE; e++) acc[e] += xv * g[e];
    }
    __shared__ float red[128][NE + 1];
#pragma unroll
    for (int e = 0; e < NE; e++) red[tid][e] = acc[e];
    __syncthreads();
    for (int off = 64; off > 0; off >>= 1) {
        if (tid < off) {
#pragma unroll
            for (int e = 0; e < NE; e++) red[tid][e] += red[tid + off][e];
        }
        __syncthreads();
    }
    if (tid == 0) {
        float lg[NE], p[NE];
        float m = -1e30f;
#pragma unroll
        for (int e = 0; e < NE; e++) { lg[e] = red[0][e]; m = fmaxf(m, lg[e]); }
        float s = 0.0f;
#pragma unroll
        for (int e = 0; e < NE; e++) { p[e] = expf(lg[e] - m); s += p[e]; }
        float inv = 1.0f / s;
#pragma unroll
        for (int e = 0; e < NE; e++) p[e] *= inv;
        int i1 = 0;
#pragma unroll
        for (int e = 1; e < NE; e++) if (p[e] > p[i1]) i1 = e;
        int i2 = (i1 == 0) ? 1 : 0;
#pragma unroll
        for (int e = 0; e < NE; e++) if (e != i1 && p[e] > p[i2]) i2 = e;
        float wsum = p[i1] + p[i2];
        g_topk_i[t * 2 + 0] = i1;
        g_topk_i[t * 2 + 1] = i2;
        g_topk_w[t * 2 + 0] = p[i1] / wsum;
        g_topk_w[t * 2 + 1] = p[i2] / wsum;
        atomicAdd(&g_counts[i1], 1);
        atomicAdd(&g_counts[i2], 1);
#pragma unroll
        for (int e = 0; e < NE; e++) {
            atomicAdd(&g_psum[e], p[e]);
            atomicAdd(&g_lsum[e], lg[e]);
        }
    }
}

// ---------------- schedule ----------------
__global__ void schedule_kernel(float* __restrict__ out, long long out_size) {
    if (threadIdx.x != 0 || blockIdx.x != 0) return;
    int tile = 0;
    for (int slot = 0; slot < NSLOT; slot++) {
        int cnt = (slot < NE) ? g_counts[slot] : NTOK;
        g_offsets[slot] = tile * TM;
        int nt = (cnt + TM - 1) / TM;
        for (int i = 0; i < nt; i++) g_tile_slot[tile++] = slot;
    }
    for (; tile < MAXTILESM; tile++) g_tile_slot[tile] = -1;
    float aux = 0.0f;
    for (int e = 0; e < NE; e++)
        aux += (g_psum[e] * (1.0f / NTOK)) * (g_lsum[e] * (1.0f / NTOK));
    aux *= (float)NE;
    if (out_size > (long long)NTOK * DDIM) out[(size_t)NTOK * DDIM] = aux;
}

// ---------------- scatter ----------------
__global__ void scatter_kernel() {
    int i = blockIdx.x * blockDim.x + threadIdx.x;
    const int total = NTOK * TOPK + NTOK * NS;
    if (i >= total) return;
    if (i < NTOK * TOPK) {
        int e = g_topk_i[i];
        int pos = atomicAdd(&g_fill[e], 1);
        int row = g_offsets[e] + pos;
        g_row_token[row] = i >> 1;
        g_row_w[row] = g_topk_w[i];
    } else {
        int j = i - NTOK * TOPK;
        int s = j / NTOK, t = j % NTOK;
        int row = g_offsets[NE + s] + t;
        g_row_token[row] = t;
        g_row_w[row] = 1.0f;
    }
}

// ----- fp16 single-pass grouped FFN GEMM, in-loop fp32->fp16 conversion -----
// PHASE1: hidden = silu(gather(x) @ W1)   K=DDIM -> g_hid (tiled fp16)
// PHASE2: out   += w_row * (hidden @ W2)  K=HDIM (atomicAdd)
// B loader reads original fp32 weights [K][N] warp-coalesced along n,
// stages fp32 in regs through the compute block, converts at STS time.
template <bool PHASE1>
__global__ __launch_bounds__(256, 2)
void ffn_mma(const float* __restrict__ x,
             const float* __restrict__ sw1, const float* __restrict__ sw2,
             const float* __restrict__ ew1, const float* __restrict__ ew2,
             float* __restrict__ out) {
    extern __shared__ char smem[];
    const int bm = blockIdx.x, bn = blockIdx.y;
    const int slot = g_tile_slot[bm];
    if (slot < 0) return;
    const int NC = PHASE1 ? NCH1 : NCH2;
    const int ND = PHASE1 ? HDIM : DDIM;
    const int row0 = bm * TM, n0 = bn * TN;
    const int tid = threadIdx.x, wid = tid >> 5, lane = tid & 31;
    int* s_tok = (int*)(smem + OFF_TOK);
    float* s_w = (float*)(smem + OFF_W);
    if (tid < TM) {
        s_tok[tid] = g_row_token[row0 + tid];
        s_w[tid]   = g_row_w[row0 + tid];
    }
    __syncthreads();

    // ---- B source: fp32 weights [K][N], lane-consecutive n ----
    const float* W;
    if (PHASE1)
        W = (slot < NE) ? ew1 + (size_t)slot * DDIM * HDIM
                        : sw1 + (size_t)(slot - NE) * DDIM * HDIM;
    else
        W = (slot < NE) ? ew2 + (size_t)slot * HDIM * DDIM
                        : sw2 + (size_t)(slot - NE) * HDIM * DDIM;
    const int bln = tid & 127;          // n within tile
    const int bkg = tid >> 7;           // k-group (0..1), 16 k each
    const float* srcBf = W + (size_t)(bkg * 16) * ND + n0 + bln;
    const int dB = bln * PITCH + bkg * 32;

    // ---- A source ----
    const float* srcAf = 0;             // phase1: fp32 x, gathered
    const uint4* srcA2 = 0;             // phase2: fp16 tiled hidden
    const int ar = tid >> 1, ah = tid & 1;
    if (PHASE1) {
        int tok = s_tok[ar]; if (tok < 0) tok = 0;
        srcAf = x + (size_t)tok * DDIM + ah * 16;
    } else {
        srcA2 = (const uint4*)g_hid + (size_t)bm * NCH2 * 512 + tid;
    }
    const int dA1 = ar * PITCH + ah * 32;
    int tDst[2];
#pragma unroll
    for (int i = 0; i < 2; i++) {
        int u = tid + i * 256;
        tDst[i] = (u >> 2) * PITCH + (u & 3) * 16;
    }

    const uint32_t sb = smem_u32(smem);
    const int warp_m = (wid >> 2) * 64;
    const int warp_n = (wid & 3) * 32;
    const int a_row = warp_m + (lane & 15);
    const int a_c8  = (lane >> 4) << 3;
    const int b_row = warp_n + (lane & 7) + ((lane >> 4) << 3);
    const int b_c8  = lane & 8;

    float acc[4][4][4];
#pragma unroll
    for (int i = 0; i < 4; i++)
#pragma unroll
        for (int j = 0; j < 4; j++)
#pragma unroll
            for (int k = 0; k < 4; k++) acc[i][j][k] = 0.0f;

    // -------- direct load + convert of chunk 0 --------
    {
        if (PHASE1) {
            float4 a0 = *(const float4*)(srcAf);
            float4 a1 = *(const float4*)(srcAf + 4);
            float4 a2 = *(const float4*)(srcAf + 8);
            float4 a3 = *(const float4*)(srcAf + 12);
            *(uint4*)(smem + AOF(0) + dA1) =
                make_uint4(pk2f(a0.x, a0.y), pk2f(a0.z, a0.w),
                           pk2f(a1.x, a1.y), pk2f(a1.z, a1.w));
            *(uint4*)(smem + AOF(0) + dA1 + 16) =
                make_uint4(pk2f(a2.x, a2.y), pk2f(a2.z, a2.w),
                           pk2f(a3.x, a3.y), pk2f(a3.z, a3.w));
        } else {
            *(uint4*)(smem + AOF(0) + tDst[0]) = srcA2[0];
            *(uint4*)(smem + AOF(0) + tDst[1]) = srcA2[256];
        }
        float bv[16];
#pragma unroll
        for (int i = 0; i < 16; i++)
            bv[i] = srcBf[(size_t)i * ND];
        *(uint4*)(smem + BOF(0) + dB) =
            make_uint4(pk2f(bv[0], bv[1]), pk2f(bv[2], bv[3]),
                       pk2f(bv[4], bv[5]), pk2f(bv[6], bv[7]));
        *(uint4*)(smem + BOF(0) + dB + 16) =
            make_uint4(pk2f(bv[8], bv[9]), pk2f(bv[10], bv[11]),
                       pk2f(bv[12], bv[13]), pk2f(bv[14], bv[15]));
    }
    __syncthreads();

    // -------- main loop: register-staged fp32 prefetch, convert at STS ------
    for (int c = 0; c < NC; c++) {
        const int buf = c & 1;
        const bool have = (c + 1 < NC);

        float sA[16], sBv[16];
        uint4 sA2a, sA2b;
        if (have) {
            if (PHASE1) {
                const float* p = srcAf + (c + 1) * KC;
                *(float4*)&sA[0]  = *(const float4*)(p);
                *(float4*)&sA[4]  = *(const float4*)(p + 4);
                *(float4*)&sA[8]  = *(const float4*)(p + 8);
                *(float4*)&sA[12] = *(const float4*)(p + 12);
            } else {
                const uint4* p = srcA2 + (size_t)(c + 1) * 512;
                sA2a = p[0]; sA2b = p[256];
            }
            const float* q = srcBf + (size_t)(c + 1) * KC * ND;
#pragma unroll
            for (int i = 0; i < 16; i++)
                sBv[i] = q[(size_t)i * ND];
        }

        // ---- compute on buffer `buf` ----
        {
            const uint32_t ab = sb + AOF(buf);
            const uint32_t bb = sb + BOF(buf);
#pragma unroll
            for (int ks = 0; ks < 2; ks++) {
                const int kk = ks * 16;
                const uint32_t baddr = (uint32_t)(b_row * PITCH + (kk + b_c8) * 2);
                const uint32_t aaddr = (uint32_t)(a_row * PITCH + (kk + a_c8) * 2);
                uint32_t bh0[4], bh1[4];
                ldsm4(bh0, bb + baddr);
                ldsm4(bh1, bb + baddr + 16 * PITCH);
#pragma unroll
                for (int mi = 0; mi < 4; mi++) {
                    uint32_t af[4];
                    ldsm4(af, ab + aaddr + mi * 16 * PITCH);
                    mmaf16(acc[mi][0], af, bh0); mmaf16(acc[mi][1], af, bh0 + 2);
                    mmaf16(acc[mi][2], af, bh1); mmaf16(acc[mi][3], af, bh1 + 2);
                }
            }
        }

        // ---- convert + STS staged chunk into other buffer ----
        if (have) {
            const int nb = (c + 1) & 1;
            if (PHASE1) {
                *(uint4*)(smem + AOF(nb) + dA1) =
                    make_uint4(pk2f(sA[0], sA[1]), pk2f(sA[2], sA[3]),
                               pk2f(sA[4], sA[5]), pk2f(sA[6], sA[7]));
                *(uint4*)(smem + AOF(nb) + dA1 + 16) =
                    make_uint4(pk2f(sA[8], sA[9]), pk2f(sA[10], sA[11]),
                               pk2f(sA[12], sA[13]), pk2f(sA[14], sA[15]));
            } else {
                *(uint4*)(smem + AOF(nb) + tDst[0]) = sA2a;
                *(uint4*)(smem + AOF(nb) + tDst[1]) = sA2b;
            }
            *(uint4*)(smem + BOF(nb) + dB) =
                make_uint4(pk2f(sBv[0], sBv[1]), pk2f(sBv[2], sBv[3]),
                           pk2f(sBv[4], sBv[5]), pk2f(sBv[6], sBv[7]));
            *(uint4*)(smem + BOF(nb) + dB + 16) =
                make_uint4(pk2f(sBv[8], sBv[9]), pk2f(sBv[10], sBv[11]),
                           pk2f(sBv[12], sBv[13]), pk2f(sBv[14], sBv[15]));
        }
        __syncthreads();
    }

    // -------- epilogue --------
    const int gid = lane >> 2, tig = lane & 3;
#pragma unroll
    for (int mi = 0; mi < 4; mi++) {
#pragma unroll
        for (int f = 0; f < 4; f++) {
            const int col = n0 + warp_n + f * 8 + tig * 2;
#pragma unroll
            for (int h = 0; h < 2; h++) {
                const int r = warp_m + mi * 16 + gid + h * 8;
                float v0 = acc[mi][f][2 * h];
                float v1 = acc[mi][f][2 * h + 1];
                if (PHASE1) {
                    v0 = v0 / (1.0f + __expf(-v0));
                    v1 = v1 / (1.0f + __expf(-v1));
                    // hidden tiled: [bm][col>>5][r][col&31] fp16
                    size_t base = ((size_t)bm * NCH2 + (col >> 5)) * ACH
                                  + (size_t)r * 32 + (col & 31);
                    *(uint32_t*)(g_hid + base) =
                        pkh(__float2half_rn(v0), __float2half_rn(v1));
                } else {
                    int tok = s_tok[r];
                    if (tok >= 0) {
                        float w = s_w[r];
                        float* op = out + (size_t)tok * DDIM + col;
                        atomicAdd(op,     w * v0);
                        atomicAdd(op + 1, w * v1);
                    }
                }
            }
        }
    }
}

// ---------------- launch ----------------
extern "C" void kernel_launch(void* const* d_in, const int* in_sizes, int n_in,
                              void* d_out, int out_size) {
    const float* x   = (const float*)d_in[0];
    const float* gw  = (const float*)d_in[1];
    const float* sw1 = (const float*)d_in[2];
    const float* sw2 = (const float*)d_in[3];
    const float* ew1 = (const float*)d_in[4];
    const float* ew2 = (const float*)d_in[5];
    float* out = (float*)d_out;

    cudaFuncSetAttribute(ffn_mma<true>,  cudaFuncAttributeMaxDynamicSharedMemorySize, SMEM_BYTES);
    cudaFuncSetAttribute(ffn_mma<false>, cudaFuncAttributeMaxDynamicSharedMemorySize, SMEM_BYTES);

    init_kernel<<<1024, 256>>>(out);
    router_kernel<<<NTOK, 128>>>(x, gw);
    schedule_kernel<<<1, 32>>>(out, (long long)out_size);
    scatter_kernel<<<(NTOK * (TOPK + NS) + 255) / 256, 256>>>();

    dim3 g1(MAXTILESM, NBN1);   // 144 x 11
    dim3 g2(MAXTILESM, NBN2);   // 144 x 16
    ffn_mma<true ><<<g1, 256, SMEM_BYTES>>>(x, sw1, sw2, ew1, ew2, out);
    ffn_mma<false><<<g2, 256, SMEM_BYTES>>>(x, sw1, sw2, ew1, ew2, out);
}

// round 14
// speedup vs baseline: 1.2597x; 1.0281x over previous
#include <cuda_runtime.h>
#include <cuda_fp16.h>
#include <cstdint>
#include <math.h>

// ---------------- problem constants ----------------
#define NTOK 4096
#define DDIM 2048
#define HDIM 1408
#define NE   16
#define NS   2
#define NSLOT (NE + NS)
#define TOPK 2
#define TM 128
#define TN 128
#define KC 64
#define MAXROWS (NTOK*TOPK + NE*TM + NTOK*NS)   // 18432
#define MAXTILESM (MAXROWS / TM)                // 144
#define NBN1 (HDIM / TN)     // 11
#define NCH1 (DDIM / KC)     // 32
#define NBN2 (DDIM / TN)     // 16
#define NCH2 (HDIM / KC)     // 22
#define WCH  8192            // chunk elems: 128 x 64 fp16
#define CHU4 1024            // uint4 per chunk

// smem tile geometry: rows of 64 fp16 (128B) + 16 pad = 144 bytes
// 144 mod 128 = 16 -> 8 ldsm rows per phase hit distinct 16B banks
#define PITCH 144
#define TILEB (128 * PITCH)          // 18432 B
#define OFF_TOK 0
#define OFF_W   512
#define OFF_TILES 1024
#define AOF(b) (OFF_TILES + (b)*2*TILEB)
#define BOF(b) (AOF(b) + TILEB)
#define SMEM_BYTES (OFF_TILES + 4*TILEB)   // 74752

// ---------------- device scratch (tiled layouts) ----------------
__device__ __align__(16) __half g_w1t[(size_t)NSLOT * NBN1 * NCH1 * WCH];
__device__ __align__(16) __half g_w2t[(size_t)NSLOT * NBN2 * NCH2 * WCH];
__device__ __align__(16) __half g_xc[(size_t)NTOK * DDIM];          // linear fp16
__device__ __align__(16) __half g_hid[(size_t)MAXTILESM * NCH2 * WCH];
__device__ int   g_row_token[MAXROWS];
__device__ float g_row_w[MAXROWS];
__device__ int   g_tile_slot[MAXTILESM];
__device__ int   g_topk_i[NTOK * TOPK];
__device__ float g_topk_w[NTOK * TOPK];
__device__ int   g_counts[NE];
__device__ int   g_fill[NE];
__device__ int   g_offsets[NSLOT];
__device__ float g_psum[NE];
__device__ float g_lsum[NE];

// ---------------- helpers ----------------
__device__ __forceinline__ uint32_t smem_u32(const void* p) {
    uint32_t a;
    asm("{ .reg .u64 t; cvta.to.shared.u64 t, %1; cvt.u32.u64 %0, t; }"
        : "=r"(a) : "l"(p));
    return a;
}
__device__ __forceinline__ void ldsm4(uint32_t* r, uint32_t addr) {
    asm volatile("ldmatrix.sync.aligned.m8n8.x4.shared.b16 {%0,%1,%2,%3}, [%4];"
                 : "=r"(r[0]), "=r"(r[1]), "=r"(r[2]), "=r"(r[3]) : "r"(addr));
}
__device__ __forceinline__ void mmaf16(float* d, const uint32_t* a, const uint32_t* b) {
    asm volatile("mma.sync.aligned.m16n8k16.row.col.f32.f16.f16.f32 "
                 "{%0,%1,%2,%3}, {%4,%5,%6,%7}, {%8,%9}, {%0,%1,%2,%3};"
                 : "+f"(d[0]), "+f"(d[1]), "+f"(d[2]), "+f"(d[3])
                 : "r"(a[0]), "r"(a[1]), "r"(a[2]), "r"(a[3]), "r"(b[0]), "r"(b[1]));
}
__device__ __forceinline__ uint32_t pkh(__half a, __half b) {
    return (uint32_t)__half_as_ushort(a) | ((uint32_t)__half_as_ushort(b) << 16);
}

// ------- weight transpose + fp16 round into KC=64 tiled layout --------------
template <int PH>
__global__ void conv_w(const float* __restrict__ ew, const float* __restrict__ sw) {
    const int K = (PH == 1) ? DDIM : HDIM;
    const int N = (PH == 1) ? HDIM : DDIM;
    const int NBN = (PH == 1) ? NBN1 : NBN2;
    const int NCH = (PH == 1) ? NCH1 : NCH2;
    __half* dst = (PH == 1) ? g_w1t : g_w2t;
    int slot = blockIdx.z;
    const float* src = (slot < NE) ? ew + (size_t)slot * K * N
                                   : sw + (size_t)(slot - NE) * K * N;
    __shared__ float t[32][33];
    int k0 = blockIdx.x * 32, n0 = blockIdx.y * 32;
    int tx = threadIdx.x, ty = threadIdx.y;   // 32, 8
#pragma unroll
    for (int i = 0; i < 4; i++)
        t[ty + i * 8][tx] = src[(size_t)(k0 + ty + i * 8) * N + n0 + tx];
    __syncthreads();
    const int k = k0 + tx;
    const int c = k >> 6;
#pragma unroll
    for (int i = 0; i < 4; i++) {
        int n = n0 + ty + i * 8;
        float v = t[tx][ty + i * 8];                 // src[k][n]
        size_t base = ((size_t)(slot * NBN + (n >> 7)) * NCH + c) * WCH
                      + (size_t)(n & 127) * KC + (k & 63);
        dst[base] = __float2half_rn(v);
    }
}

// ---------------- x fp16 round (linear layout) ----------------
__global__ void conv_x(const float* __restrict__ x) {
    size_t i = ((size_t)blockIdx.x * blockDim.x + threadIdx.x) * 4;
    if (i >= (size_t)NTOK * DDIM) return;
    float4 v = *(const float4*)(x + i);
    __half2 h0 = __floats2half2_rn(v.x, v.y);
    __half2 h1 = __floats2half2_rn(v.z, v.w);
    *(uint2*)(g_xc + i) = make_uint2(*(uint32_t*)&h0, *(uint32_t*)&h1);
}

// ---------------- init ----------------
__global__ void init_kernel(float* __restrict__ out) {
    int idx = blockIdx.x * blockDim.x + threadIdx.x;
    int stride = gridDim.x * blockDim.x;
    for (size_t i = idx; i < (size_t)NTOK * DDIM; i += stride) out[i] = 0.0f;
    for (int i = idx; i < MAXROWS; i += stride) g_row_token[i] = -1;
    if (idx < NE) {
        g_counts[idx] = 0; g_fill[idx] = 0;
        g_psum[idx] = 0.0f; g_lsum[idx] = 0.0f;
    }
}

// ---------------- router ----------------
__global__ void router_kernel(const float* __restrict__ x,
                              const float* __restrict__ gw) {
    int t = blockIdx.x;
    int tid = threadIdx.x;
    float acc[NE];
#pragma unroll
    for (int e = 0; e < NE; e++) acc[e] = 0.0f;
    const float* xr = x + (size_t)t * DDIM;
    for (int d = tid; d < DDIM; d += 128) {
        float xv = xr[d];
        const float* g = gw + d * NE;
#pragma unroll
        for (int e = 0; e < NE; e++) acc[e] += xv * g[e];
    }
    __shared__ float red[128][NE + 1];
#pragma unroll
    for (int e = 0; e < NE; e++) red[tid][e] = acc[e];
    __syncthreads();
    for (int off = 64; off > 0; off >>= 1) {
        if (tid < off) {
#pragma unroll
            for (int e = 0; e < NE; e++) red[tid][e] += red[tid + off][e];
        }
        __syncthreads();
    }
    if (tid == 0) {
        float lg[NE], p[NE];
        float m = -1e30f;
#pragma unroll
        for (int e = 0; e < NE; e++) { lg[e] = red[0][e]; m = fmaxf(m, lg[e]); }
        float s = 0.0f;
#pragma unroll
        for (int e = 0; e < NE; e++) { p[e] = expf(lg[e] - m); s += p[e]; }
        float inv = 1.0f / s;
#pragma unroll
        for (int e = 0; e < NE; e++) p[e] *= inv;
        int i1 = 0;
#pragma unroll
        for (int e = 1; e < NE; e++) if (p[e] > p[i1]) i1 = e;
        int i2 = (i1 == 0) ? 1 : 0;
#pragma unroll
        for (int e = 0; e < NE; e++) if (e != i1 && p[e] > p[i2]) i2 = e;
        float wsum = p[i1] + p[i2];
        g_topk_i[t * 2 + 0] = i1;
        g_topk_i[t * 2 + 1] = i2;
        g_topk_w[t * 2 + 0] = p[i1] / wsum;
        g_topk_w[t * 2 + 1] = p[i2] / wsum;
        atomicAdd(&g_counts[i1], 1);
        atomicAdd(&g_counts[i2], 1);
#pragma unroll
        for (int e = 0; e < NE; e++) {
            atomicAdd(&g_psum[e], p[e]);
            atomicAdd(&g_lsum[e], lg[e]);
        }
    }
}

// ---------------- schedule ----------------
__global__ void schedule_kernel(float* __restrict__ out, long long out_size) {
    if (threadIdx.x != 0 || blockIdx.x != 0) return;
    int tile = 0;
    for (int slot = 0; slot < NSLOT; slot++) {
        int cnt = (slot < NE) ? g_counts[slot] : NTOK;
        g_offsets[slot] = tile * TM;
        int nt = (cnt + TM - 1) / TM;
        for (int i = 0; i < nt; i++) g_tile_slot[tile++] = slot;
    }
    for (; tile < MAXTILESM; tile++) g_tile_slot[tile] = -1;
    float aux = 0.0f;
    for (int e = 0; e < NE; e++)
        aux += (g_psum[e] * (1.0f / NTOK)) * (g_lsum[e] * (1.0f / NTOK));
    aux *= (float)NE;
    if (out_size > (long long)NTOK * DDIM) out[(size_t)NTOK * DDIM] = aux;
}

// ---------------- scatter ----------------
__global__ void scatter_kernel() {
    int i = blockIdx.x * blockDim.x + threadIdx.x;
    const int total = NTOK * TOPK + NTOK * NS;
    if (i >= total) return;
    if (i < NTOK * TOPK) {
        int e = g_topk_i[i];
        int pos = atomicAdd(&g_fill[e], 1);
        int row = g_offsets[e] + pos;
        g_row_token[row] = i >> 1;
        g_row_w[row] = g_topk_w[i];
    } else {
        int j = i - NTOK * TOPK;
        int s = j / NTOK, t = j % NTOK;
        int row = g_offsets[NE + s] + t;
        g_row_token[row] = t;
        g_row_w[row] = 1.0f;
    }
}

// ----- fp16 single-pass grouped FFN GEMM, KC=64 chunks ----------------------
// PHASE1: hidden = silu(gather(x) @ W1)   K=DDIM -> g_hid (tiled fp16)
// PHASE2: out   += w_row * (hidden @ W2)  K=HDIM (atomicAdd)
template <bool PHASE1>
__global__ __launch_bounds__(256, 2)
void ffn_mma(float* __restrict__ out) {
    extern __shared__ char smem[];
    const int bm = blockIdx.x, bn = blockIdx.y;
    const int slot = g_tile_slot[bm];
    if (slot < 0) return;
    const int NC = PHASE1 ? NCH1 : NCH2;
    const int row0 = bm * TM, n0 = bn * TN;
    const int tid = threadIdx.x, wid = tid >> 5, lane = tid & 31;
    int* s_tok = (int*)(smem + OFF_TOK);
    float* s_w = (float*)(smem + OFF_W);
    if (tid < TM) {
        s_tok[tid] = g_row_token[row0 + tid];
        s_w[tid]   = g_row_w[row0 + tid];
    }
    __syncthreads();

    // ---- loader offsets: tile = 1024 u4/chunk, 4 per thread ----
    int tDst[4];
#pragma unroll
    for (int i = 0; i < 4; i++) {
        int u = tid + i * 256;
        tDst[i] = (u >> 3) * PITCH + (u & 7) * 16;
    }

    const uint4* srcB = PHASE1
        ? (const uint4*)g_w1t + (size_t)(slot * NBN1 + bn) * NCH1 * CHU4
        : (const uint4*)g_w2t + (size_t)(slot * NBN2 + bn) * NCH2 * CHU4;
    const uint4* srcA2 = 0;
    const uint4* srcA1 = 0;
    const int ah = tid & 1;                  // phase1: which 4 u4 of the row chunk
    if (PHASE1) {
        int tok = s_tok[tid >> 1]; if (tok < 0) tok = 0;
        srcA1 = (const uint4*)(g_xc + (size_t)tok * DDIM) + ah * 4;
    } else {
        srcA2 = (const uint4*)g_hid + (size_t)bm * NCH2 * CHU4;
    }
    const int dA1 = (tid >> 1) * PITCH + ah * 64;

    const uint32_t sb = smem_u32(smem);
    const int warp_m = (wid >> 2) * 64;
    const int warp_n = (wid & 3) * 32;
    const int a_row = warp_m + (lane & 15);
    const int a_c8  = (lane >> 4) << 3;
    const int b_row = warp_n + (lane & 7) + ((lane >> 4) << 3);
    const int b_c8  = lane & 8;

    float acc[4][4][4];
#pragma unroll
    for (int i = 0; i < 4; i++)
#pragma unroll
        for (int j = 0; j < 4; j++)
#pragma unroll
            for (int k = 0; k < 4; k++) acc[i][j][k] = 0.0f;

    // -------- direct load of chunk 0 --------
    {
        if (PHASE1) {
            char* base = smem + AOF(0) + dA1;
#pragma unroll
            for (int i = 0; i < 4; i++)
                *(uint4*)(base + i * 16) = srcA1[i];
        } else {
#pragma unroll
            for (int i = 0; i < 4; i++)
                *(uint4*)(smem + AOF(0) + tDst[i]) = srcA2[tid + i * 256];
        }
#pragma unroll
        for (int i = 0; i < 4; i++)
            *(uint4*)(smem + BOF(0) + tDst[i]) = srcB[tid + i * 256];
    }
    __syncthreads();

    // -------- main loop --------
    for (int c = 0; c < NC; c++) {
        const int buf = c & 1;
        const bool have = (c + 1 < NC);

        uint4 sA[4], sB[4];
        if (have) {
            if (PHASE1) {
                const uint4* p = srcA1 + (size_t)(c + 1) * 8;
#pragma unroll
                for (int i = 0; i < 4; i++) sA[i] = p[i];
            } else {
                const uint4* p = srcA2 + (size_t)(c + 1) * CHU4;
#pragma unroll
                for (int i = 0; i < 4; i++) sA[i] = p[tid + i * 256];
            }
            const uint4* q = srcB + (size_t)(c + 1) * CHU4;
#pragma unroll
            for (int i = 0; i < 4; i++) sB[i] = q[tid + i * 256];
        }

        // ---- compute on buffer `buf`: 4 k-steps of 16 ----
        {
            const uint32_t ab = sb + AOF(buf);
            const uint32_t bb = sb + BOF(buf);
#pragma unroll
            for (int ks = 0; ks < 4; ks++) {
                const int kk = ks * 16;
                const uint32_t baddr = (uint32_t)(b_row * PITCH + (kk + b_c8) * 2);
                const uint32_t aaddr = (uint32_t)(a_row * PITCH + (kk + a_c8) * 2);
                uint32_t bh0[4], bh1[4];
                ldsm4(bh0, bb + baddr);
                ldsm4(bh1, bb + baddr + 16 * PITCH);
#pragma unroll
                for (int mi = 0; mi < 4; mi++) {
                    uint32_t af[4];
                    ldsm4(af, ab + aaddr + mi * 16 * PITCH);
                    mmaf16(acc[mi][0], af, bh0); mmaf16(acc[mi][1], af, bh0 + 2);
                    mmaf16(acc[mi][2], af, bh1); mmaf16(acc[mi][3], af, bh1 + 2);
                }
            }
        }

        // ---- STS staged chunk into other buffer ----
        if (have) {
            const int nb = (c + 1) & 1;
            if (PHASE1) {
                char* base = smem + AOF(nb) + dA1;
#pragma unroll
                for (int i = 0; i < 4; i++)
                    *(uint4*)(base + i * 16) = sA[i];
            } else {
#pragma unroll
                for (int i = 0; i < 4; i++)
                    *(uint4*)(smem + AOF(nb) + tDst[i]) = sA[i];
            }
#pragma unroll
            for (int i = 0; i < 4; i++)
                *(uint4*)(smem + BOF(nb) + tDst[i]) = sB[i];
        }
        __syncthreads();
    }

    // -------- epilogue --------
    const int gid = lane >> 2, tig = lane & 3;
#pragma unroll
    for (int mi = 0; mi < 4; mi++) {
#pragma unroll
        for (int f = 0; f < 4; f++) {
            const int col = n0 + warp_n + f * 8 + tig * 2;
#pragma unroll
            for (int h = 0; h < 2; h++) {
                const int r = warp_m + mi * 16 + gid + h * 8;
                float v0 = acc[mi][f][2 * h];
                float v1 = acc[mi][f][2 * h + 1];
                if (PHASE1) {
                    v0 = v0 / (1.0f + __expf(-v0));
                    v1 = v1 / (1.0f + __expf(-v1));
                    // hidden tiled: [bm][col>>6][r][col&63] fp16
                    size_t base = ((size_t)bm * NCH2 + (col >> 6)) * WCH
                                  + (size_t)r * KC + (col & 63);
                    *(uint32_t*)(g_hid + base) =
                        pkh(__float2half_rn(v0), __float2half_rn(v1));
                } else {
                    int tok = s_tok[r];
                    if (tok >= 0) {
                        float w = s_w[r];
                        float* op = out + (size_t)tok * DDIM + col;
                        atomicAdd(op,     w * v0);
                        atomicAdd(op + 1, w * v1);
                    }
                }
            }
        }
    }
}

// ---------------- launch ----------------
extern "C" void kernel_launch(void* const* d_in, const int* in_sizes, int n_in,
                              void* d_out, int out_size) {
    const float* x   = (const float*)d_in[0];
    const float* gw  = (const float*)d_in[1];
    const float* sw1 = (const float*)d_in[2];
    const float* sw2 = (const float*)d_in[3];
    const float* ew1 = (const float*)d_in[4];
    const float* ew2 = (const float*)d_in[5];
    float* out = (float*)d_out;

    cudaFuncSetAttribute(ffn_mma<true>,  cudaFuncAttributeMaxDynamicSharedMemorySize, SMEM_BYTES);
    cudaFuncSetAttribute(ffn_mma<false>, cudaFuncAttributeMaxDynamicSharedMemorySize, SMEM_BYTES);

    init_kernel<<<1024, 256>>>(out);
    router_kernel<<<NTOK, 128>>>(x, gw);
    schedule_kernel<<<1, 32>>>(out, (long long)out_size);
    scatter_kernel<<<(NTOK * (TOPK + NS) + 255) / 256, 256>>>();

    dim3 tb(32, 8);
    conv_w<1><<<dim3(DDIM / 32, HDIM / 32, NSLOT), tb>>>(ew1, sw1);
    conv_w<2><<<dim3(HDIM / 32, DDIM / 32, NSLOT), tb>>>(ew2, sw2);
    conv_x<<<(NTOK * DDIM / 4 + 255) / 256, 256>>>(x);

    dim3 g1(MAXTILESM, NBN1);   // 144 x 11
    dim3 g2(MAXTILESM, NBN2);   // 144 x 16
    ffn_mma<true ><<<g1, 256, SMEM_BYTES>>>(out);
    ffn_mma<false><<<g2, 256, SMEM_BYTES>>>(out);
}

// round 15
// speedup vs baseline: 1.2731x; 1.0107x over previous
#include <cuda_runtime.h>
#include <cuda_fp16.h>
#include <cstdint>
#include <math.h>

// ---------------- problem constants ----------------
#define NTOK 4096
#define DDIM 2048
#define HDIM 1408
#define NE   16
#define NS   2
#define NSLOT (NE + NS)
#define TOPK 2
#define TM 128
#define TN 128
#define KC 64
#define MAXROWS (NTOK*TOPK + NE*TM + NTOK*NS)   // 18432
#define MAXTILESM (MAXROWS / TM)                // 144
#define NBN1 (HDIM / TN)     // 11
#define NCH1 (DDIM / KC)     // 32
#define NBN2 (DDIM / TN)     // 16
#define NCH2 (HDIM / KC)     // 22
#define WCH  8192            // chunk elems: 128 x 64 fp16
#define CHU4 1024            // uint4 per chunk

// smem tile geometry: rows of 64 fp16 (128B) + 16 pad = 144 bytes
#define PITCH 144
#define TILEB (128 * PITCH)          // 18432 B
#define OFF_TOK 0
#define OFF_W   512
#define OFF_TILES 1024
#define AOF(b) (OFF_TILES + (b)*2*TILEB)
#define BOF(b) (AOF(b) + TILEB)
#define SMEM_BYTES (OFF_TILES + 4*TILEB)   // 74752

// ---------------- device scratch (tiled layouts) ----------------
__device__ __align__(16) __half g_w1t[(size_t)NSLOT * NBN1 * NCH1 * WCH];
__device__ __align__(16) __half g_w2t[(size_t)NSLOT * NBN2 * NCH2 * WCH];
__device__ __align__(16) __half g_xc[(size_t)NTOK * DDIM];          // linear fp16
__device__ __align__(16) __half g_hid[(size_t)MAXTILESM * NCH2 * WCH];
__device__ int   g_row_token[MAXROWS];
__device__ float g_row_w[MAXROWS];
__device__ int   g_tile_slot[MAXTILESM];
__device__ int   g_topk_i[NTOK * TOPK];
__device__ float g_topk_w[NTOK * TOPK];
__device__ int   g_counts[NE];
__device__ int   g_fill[NE];
__device__ int   g_offsets[NSLOT];
__device__ float g_psum[NE];
__device__ float g_lsum[NE];

// ---------------- helpers ----------------
__device__ __forceinline__ uint32_t smem_u32(const void* p) {
    uint32_t a;
    asm("{ .reg .u64 t; cvta.to.shared.u64 t, %1; cvt.u32.u64 %0, t; }"
        : "=r"(a) : "l"(p));
    return a;
}
__device__ __forceinline__ void ldsm4(uint32_t* r, uint32_t addr) {
    asm volatile("ldmatrix.sync.aligned.m8n8.x4.shared.b16 {%0,%1,%2,%3}, [%4];"
                 : "=r"(r[0]), "=r"(r[1]), "=r"(r[2]), "=r"(r[3]) : "r"(addr));
}
__device__ __forceinline__ void mmaf16(float* d, const uint32_t* a, const uint32_t* b) {
    asm volatile("mma.sync.aligned.m16n8k16.row.col.f32.f16.f16.f32 "
                 "{%0,%1,%2,%3}, {%4,%5,%6,%7}, {%8,%9}, {%0,%1,%2,%3};"
                 : "+f"(d[0]), "+f"(d[1]), "+f"(d[2]), "+f"(d[3])
                 : "r"(a[0]), "r"(a[1]), "r"(a[2]), "r"(a[3]), "r"(b[0]), "r"(b[1]));
}
__device__ __forceinline__ uint32_t pkh(__half a, __half b) {
    return (uint32_t)__half_as_ushort(a) | ((uint32_t)__half_as_ushort(b) << 16);
}

// ------- weight transpose + fp16 round into KC=64 tiled layout --------------
template <int PH>
__global__ void conv_w(const float* __restrict__ ew, const float* __restrict__ sw) {
    const int K = (PH == 1) ? DDIM : HDIM;
    const int N = (PH == 1) ? HDIM : DDIM;
    const int NBN = (PH == 1) ? NBN1 : NBN2;
    const int NCH = (PH == 1) ? NCH1 : NCH2;
    __half* dst = (PH == 1) ? g_w1t : g_w2t;
    int slot = blockIdx.z;
    const float* src = (slot < NE) ? ew + (size_t)slot * K * N
                                   : sw + (size_t)(slot - NE) * K * N;
    __shared__ float t[32][33];
    int k0 = blockIdx.x * 32, n0 = blockIdx.y * 32;
    int tx = threadIdx.x, ty = threadIdx.y;   // 32, 8
#pragma unroll
    for (int i = 0; i < 4; i++)
        t[ty + i * 8][tx] = src[(size_t)(k0 + ty + i * 8) * N + n0 + tx];
    __syncthreads();
    const int k = k0 + tx;
    const int c = k >> 6;
#pragma unroll
    for (int i = 0; i < 4; i++) {
        int n = n0 + ty + i * 8;
        float v = t[tx][ty + i * 8];                 // src[k][n]
        size_t base = ((size_t)(slot * NBN + (n >> 7)) * NCH + c) * WCH
                      + (size_t)(n & 127) * KC + (k & 63);
        dst[base] = __float2half_rn(v);
    }
}

// ---------------- x fp16 round (linear layout) ----------------
__global__ void conv_x(const float* __restrict__ x) {
    size_t i = ((size_t)blockIdx.x * blockDim.x + threadIdx.x) * 4;
    if (i >= (size_t)NTOK * DDIM) return;
    float4 v = *(const float4*)(x + i);
    __half2 h0 = __floats2half2_rn(v.x, v.y);
    __half2 h1 = __floats2half2_rn(v.z, v.w);
    *(uint2*)(g_xc + i) = make_uint2(*(uint32_t*)&h0, *(uint32_t*)&h1);
}

// ---------------- init ----------------
__global__ void init_kernel(float* __restrict__ out) {
    int idx = blockIdx.x * blockDim.x + threadIdx.x;
    int stride = gridDim.x * blockDim.x;
    for (size_t i = idx; i < (size_t)NTOK * DDIM; i += stride) out[i] = 0.0f;
    for (int i = idx; i < MAXROWS; i += stride) g_row_token[i] = -1;
    if (idx < NE) {
        g_counts[idx] = 0; g_fill[idx] = 0;
        g_psum[idx] = 0.0f; g_lsum[idx] = 0.0f;
    }
}

// ---------------- router ----------------
__global__ void router_kernel(const float* __restrict__ x,
                              const float* __restrict__ gw) {
    int t = blockIdx.x;
    int tid = threadIdx.x;
    float acc[NE];
#pragma unroll
    for (int e = 0; e < NE; e++) acc[e] = 0.0f;
    const float* xr = x + (size_t)t * DDIM;
    for (int d = tid; d < DDIM; d += 128) {
        float xv = xr[d];
        const float* g = gw + d * NE;
#pragma unroll
        for (int e = 0; e < NE; e++) acc[e] += xv * g[e];
    }
    __shared__ float red[128][NE + 1];
#pragma unroll
    for (int e = 0; e < NE; e++) red[tid][e] = acc[e];
    __syncthreads();
    for (int off = 64; off > 0; off >>= 1) {
        if (tid < off) {
#pragma unroll
            for (int e = 0; e < NE; e++) red[tid][e] += red[tid + off][e];
        }
        __syncthreads();
    }
    if (tid == 0) {
        float lg[NE], p[NE];
        float m = -1e30f;
#pragma unroll
        for (int e = 0; e < NE; e++) { lg[e] = red[0][e]; m = fmaxf(m, lg[e]); }
        float s = 0.0f;
#pragma unroll
        for (int e = 0; e < NE; e++) { p[e] = expf(lg[e] - m); s += p[e]; }
        float inv = 1.0f / s;
#pragma unroll
        for (int e = 0; e < NE; e++) p[e] *= inv;
        int i1 = 0;
#pragma unroll
        for (int e = 1; e < NE; e++) if (p[e] > p[i1]) i1 = e;
        int i2 = (i1 == 0) ? 1 : 0;
#pragma unroll
        for (int e = 0; e < NE; e++) if (e != i1 && p[e] > p[i2]) i2 = e;
        float wsum = p[i1] + p[i2];
        g_topk_i[t * 2 + 0] = i1;
        g_topk_i[t * 2 + 1] = i2;
        g_topk_w[t * 2 + 0] = p[i1] / wsum;
        g_topk_w[t * 2 + 1] = p[i2] / wsum;
        atomicAdd(&g_counts[i1], 1);
        atomicAdd(&g_counts[i2], 1);
#pragma unroll
        for (int e = 0; e < NE; e++) {
            atomicAdd(&g_psum[e], p[e]);
            atomicAdd(&g_lsum[e], lg[e]);
        }
    }
}

// ---------------- schedule ----------------
__global__ void schedule_kernel(float* __restrict__ out, long long out_size) {
    if (threadIdx.x != 0 || blockIdx.x != 0) return;
    int tile = 0;
    for (int slot = 0; slot < NSLOT; slot++) {
        int cnt = (slot < NE) ? g_counts[slot] : NTOK;
        g_offsets[slot] = tile * TM;
        int nt = (cnt + TM - 1) / TM;
        for (int i = 0; i < nt; i++) g_tile_slot[tile++] = slot;
    }
    for (; tile < MAXTILESM; tile++) g_tile_slot[tile] = -1;
    float aux = 0.0f;
    for (int e = 0; e < NE; e++)
        aux += (g_psum[e] * (1.0f / NTOK)) * (g_lsum[e] * (1.0f / NTOK));
    aux *= (float)NE;
    if (out_size > (long long)NTOK * DDIM) out[(size_t)NTOK * DDIM] = aux;
}

// ---------------- scatter ----------------
__global__ void scatter_kernel() {
    int i = blockIdx.x * blockDim.x + threadIdx.x;
    const int total = NTOK * TOPK + NTOK * NS;
    if (i >= total) return;
    if (i < NTOK * TOPK) {
        int e = g_topk_i[i];
        int pos = atomicAdd(&g_fill[e], 1);
        int row = g_offsets[e] + pos;
        g_row_token[row] = i >> 1;
        g_row_w[row] = g_topk_w[i];
    } else {
        int j = i - NTOK * TOPK;
        int s = j / NTOK, t = j % NTOK;
        int row = g_offsets[NE + s] + t;
        g_row_token[row] = t;
        g_row_w[row] = 1.0f;
    }
}

// ----- fp16 single-pass grouped FFN GEMM, KC=64 chunks ----------------------
// PHASE1: hidden = silu(gather(x) @ W1)   K=DDIM -> g_hid (tiled fp16)
// PHASE2: out   += w_row * (hidden @ W2)  K=HDIM (atomicAdd)
template <bool PHASE1>
__global__ __launch_bounds__(256, 2)
void ffn_mma(float* __restrict__ out) {
    extern __shared__ char smem[];
    const int bm = blockIdx.x, bn = blockIdx.y;
    const int slot = g_tile_slot[bm];
    if (slot < 0) return;
    const int NC = PHASE1 ? NCH1 : NCH2;
    const int row0 = bm * TM, n0 = bn * TN;
    const int tid = threadIdx.x, wid = tid >> 5, lane = tid & 31;
    int* s_tok = (int*)(smem + OFF_TOK);
    float* s_w = (float*)(smem + OFF_W);
    if (tid < TM) {
        s_tok[tid] = g_row_token[row0 + tid];
        s_w[tid]   = g_row_w[row0 + tid];
    }
    __syncthreads();

    // ---- loader offsets: tile = 1024 u4/chunk, 4 per thread ----
    int tDst[4];
#pragma unroll
    for (int i = 0; i < 4; i++) {
        int u = tid + i * 256;
        tDst[i] = (u >> 3) * PITCH + (u & 7) * 16;
    }

    const uint4* srcB = PHASE1
        ? (const uint4*)g_w1t + (size_t)(slot * NBN1 + bn) * NCH1 * CHU4
        : (const uint4*)g_w2t + (size_t)(slot * NBN2 + bn) * NCH2 * CHU4;
    const uint4* srcA2 = 0;
    const uint4* srcA1 = 0;
    const int ah = tid & 1;                  // phase1: which 4 u4 of the row chunk
    if (PHASE1) {
        int tok = s_tok[tid >> 1]; if (tok < 0) tok = 0;
        srcA1 = (const uint4*)(g_xc + (size_t)tok * DDIM) + ah * 4;
    } else {
        srcA2 = (const uint4*)g_hid + (size_t)bm * NCH2 * CHU4;
    }
    const int dA1 = (tid >> 1) * PITCH + ah * 64;

    const uint32_t sb = smem_u32(smem);
    const int warp_m = (wid >> 2) * 64;
    const int warp_n = (wid & 3) * 32;
    const int a_row = warp_m + (lane & 15);
    const int a_c8  = (lane >> 4) << 3;
    const int b_row = warp_n + (lane & 7) + ((lane >> 4) << 3);
    const int b_c8  = lane & 8;

    float acc[4][4][4];
#pragma unroll
    for (int i = 0; i < 4; i++)
#pragma unroll
        for (int j = 0; j < 4; j++)
#pragma unroll
            for (int k = 0; k < 4; k++) acc[i][j][k] = 0.0f;

    // -------- direct load of chunk 0 --------
    {
        if (PHASE1) {
            char* base = smem + AOF(0) + dA1;
#pragma unroll
            for (int i = 0; i < 4; i++)
                *(uint4*)(base + i * 16) = srcA1[i];
        } else {
#pragma unroll
            for (int i = 0; i < 4; i++)
                *(uint4*)(smem + AOF(0) + tDst[i]) = srcA2[tid + i * 256];
        }
#pragma unroll
        for (int i = 0; i < 4; i++)
            *(uint4*)(smem + BOF(0) + tDst[i]) = srcB[tid + i * 256];
    }
    __syncthreads();

    // -------- main loop --------
    for (int c = 0; c < NC; c++) {
        const int buf = c & 1;
        const bool have = (c + 1 < NC);

        uint4 sA[4], sB[4];
        if (have) {
            if (PHASE1) {
                const uint4* p = srcA1 + (size_t)(c + 1) * 8;
#pragma unroll
                for (int i = 0; i < 4; i++) sA[i] = p[i];
            } else {
                const uint4* p = srcA2 + (size_t)(c + 1) * CHU4;
#pragma unroll
                for (int i = 0; i < 4; i++) sA[i] = p[tid + i * 256];
            }
            const uint4* q = srcB + (size_t)(c + 1) * CHU4;
#pragma unroll
            for (int i = 0; i < 4; i++) sB[i] = q[tid + i * 256];
        }

        // ---- compute on buffer `buf`: 4 k-steps of 16 ----
        {
            const uint32_t ab = sb + AOF(buf);
            const uint32_t bb = sb + BOF(buf);
#pragma unroll
            for (int ks = 0; ks < 4; ks++) {
                const int kk = ks * 16;
                const uint32_t baddr = (uint32_t)(b_row * PITCH + (kk + b_c8) * 2);
                const uint32_t aaddr = (uint32_t)(a_row * PITCH + (kk + a_c8) * 2);
                uint32_t bh0[4], bh1[4];
                ldsm4(bh0, bb + baddr);
                ldsm4(bh1, bb + baddr + 16 * PITCH);
#pragma unroll
                for (int mi = 0; mi < 4; mi++) {
                    uint32_t af[4];
                    ldsm4(af, ab + aaddr + mi * 16 * PITCH);
                    mmaf16(acc[mi][0], af, bh0); mmaf16(acc[mi][1], af, bh0 + 2);
                    mmaf16(acc[mi][2], af, bh1); mmaf16(acc[mi][3], af, bh1 + 2);
                }
            }
        }

        // ---- STS staged chunk into other buffer ----
        if (have) {
            const int nb = (c + 1) & 1;
            if (PHASE1) {
                char* base = smem + AOF(nb) + dA1;
#pragma unroll
                for (int i = 0; i < 4; i++)
                    *(uint4*)(base + i * 16) = sA[i];
            } else {
#pragma unroll
                for (int i = 0; i < 4; i++)
                    *(uint4*)(smem + AOF(nb) + tDst[i]) = sA[i];
            }
#pragma unroll
            for (int i = 0; i < 4; i++)
                *(uint4*)(smem + BOF(nb) + tDst[i]) = sB[i];
        }
        __syncthreads();
    }

    // -------- epilogue --------
    const int gid = lane >> 2, tig = lane & 3;
#pragma unroll
    for (int mi = 0; mi < 4; mi++) {
#pragma unroll
        for (int f = 0; f < 4; f++) {
            const int col = n0 + warp_n + f * 8 + tig * 2;
#pragma unroll
            for (int h = 0; h < 2; h++) {
                const int r = warp_m + mi * 16 + gid + h * 8;
                float v0 = acc[mi][f][2 * h];
                float v1 = acc[mi][f][2 * h + 1];
                if (PHASE1) {
                    v0 = v0 / (1.0f + __expf(-v0));
                    v1 = v1 / (1.0f + __expf(-v1));
                    // hidden tiled: [bm][col>>6][r][col&63] fp16
                    size_t base = ((size_t)bm * NCH2 + (col >> 6)) * WCH
                                  + (size_t)r * KC + (col & 63);
                    *(uint32_t*)(g_hid + base) =
                        pkh(__float2half_rn(v0), __float2half_rn(v1));
                } else {
                    int tok = s_tok[r];
                    if (tok >= 0) {
                        float w = s_w[r];
                        float* op = out + (size_t)tok * DDIM + col;
                        atomicAdd(op,     w * v0);
                        atomicAdd(op + 1, w * v1);
                    }
                }
            }
        }
    }
}

// ---------------- launch: multi-stream fork/join inside graph capture -------
extern "C" void kernel_launch(void* const* d_in, const int* in_sizes, int n_in,
                              void* d_out, int out_size) {
    const float* x   = (const float*)d_in[0];
    const float* gw  = (const float*)d_in[1];
    const float* sw1 = (const float*)d_in[2];
    const float* sw2 = (const float*)d_in[3];
    const float* ew1 = (const float*)d_in[4];
    const float* ew2 = (const float*)d_in[5];
    float* out = (float*)d_out;

    // one-time resource setup (no device memory involved; identical work per call)
    static cudaStream_t sA = 0, sB = 0, sC = 0;
    static cudaEvent_t eFork = 0, eA = 0, eB = 0, eC = 0;
    static bool ready = false;
    if (!ready) {
        cudaStreamCreateWithFlags(&sA, cudaStreamNonBlocking);
        cudaStreamCreateWithFlags(&sB, cudaStreamNonBlocking);
        cudaStreamCreateWithFlags(&sC, cudaStreamNonBlocking);
        cudaEventCreateWithFlags(&eFork, cudaEventDisableTiming);
        cudaEventCreateWithFlags(&eA, cudaEventDisableTiming);
        cudaEventCreateWithFlags(&eB, cudaEventDisableTiming);
        cudaEventCreateWithFlags(&eC, cudaEventDisableTiming);
        cudaFuncSetAttribute(ffn_mma<true>,  cudaFuncAttributeMaxDynamicSharedMemorySize, SMEM_BYTES);
        cudaFuncSetAttribute(ffn_mma<false>, cudaFuncAttributeMaxDynamicSharedMemorySize, SMEM_BYTES);
        ready = true;
    }

    dim3 tb(32, 8);

    // fork: record on the (captured) default stream, branch streams wait on it
    cudaEventRecord(eFork, 0);
    cudaStreamWaitEvent(sA, eFork, 0);
    cudaStreamWaitEvent(sB, eFork, 0);
    cudaStreamWaitEvent(sC, eFork, 0);

    // branch A: W1 conversion (needed by ffn1)
    conv_w<1><<<dim3(DDIM / 32, HDIM / 32, NSLOT), tb, 0, sA>>>(ew1, sw1);
    cudaEventRecord(eA, sA);
    // branch B: W2 conversion (needed only by ffn2 — hides under ffn1)
    conv_w<2><<<dim3(HDIM / 32, DDIM / 32, NSLOT), tb, 0, sB>>>(ew2, sw2);
    cudaEventRecord(eB, sB);
    // branch C: x conversion (needed by ffn1)
    conv_x<<<(NTOK * DDIM / 4 + 255) / 256, 256, 0, sC>>>(x);
    cudaEventRecord(eC, sC);

    // main chain on default stream
    init_kernel<<<1024, 256>>>(out);
    router_kernel<<<NTOK, 128>>>(x, gw);
    schedule_kernel<<<1, 32>>>(out, (long long)out_size);
    scatter_kernel<<<(NTOK * (TOPK + NS) + 255) / 256, 256>>>();

    // join A and C before phase 1
    cudaStreamWaitEvent(0, eA, 0);
    cudaStreamWaitEvent(0, eC, 0);
    dim3 g1(MAXTILESM, NBN1);   // 144 x 11
    ffn_mma<true ><<<g1, 256, SMEM_BYTES>>>(out);

    // join B before phase 2
    cudaStreamWaitEvent(0, eB, 0);
    dim3 g2(MAXTILESM, NBN2);   // 144 x 16
    ffn_mma<false><<<g2, 256, SMEM_BYTES>>>(out);
}